// round 17
// baseline (speedup 1.0000x reference)
#include <cuda_runtime.h>
#include <cuda_bf16.h>
#include <math_constants.h>
#include <cstdint>

// Problem constants
#define S_LEN 2048
#define NBATCH 4
#define NH 16
#define DKH 64
#define DM 1024
#define NTOK (S_LEN * NBATCH)   // 8192 tokens
#define QKV_ELEMS (NBATCH * NH * S_LEN * DKH)
#define ACT_ELEMS (NTOK * DM)

// Q projection scale: (1/sqrt(64)) * log2(e), so softmax uses bare exp2.
#define QSCALE 0.18033688011112042f

// ---------------------------------------------------------------------------
// Scratch (allocation-free rule: __device__ globals)
// ---------------------------------------------------------------------------
__device__ __nv_bfloat16 g_axh[3 * ACT_ELEMS];   // q/k/v input activations hi
__device__ __nv_bfloat16 g_axl[3 * ACT_ELEMS];
__device__ __nv_bfloat16 g_qkvh[3 * QKV_ELEMS];  // projected Q/K/V hi ([B,H,S,64])
__device__ __nv_bfloat16 g_qkvl[3 * QKV_ELEMS];
__device__ __nv_bfloat16 g_cxh[ACT_ELEMS];       // context hi ([B,S,D])
__device__ __nv_bfloat16 g_cxl[ACT_ELEMS];
__device__ __nv_bfloat16 g_wwh[4 * DM * DM];     // Wq,Wk,Wv,Wo hi
__device__ __nv_bfloat16 g_wwl[4 * DM * DM];

// ---------------------------------------------------------------------------
// Primitives (sm_80 ISA — compile on plain sm_103 target; no sm_103a gates)
// ---------------------------------------------------------------------------
__device__ __forceinline__ uint32_t smem_u32(const void* p) {
    uint32_t a;
    asm("{ .reg .u64 t; cvta.to.shared.u64 t, %1; cvt.u32.u64 %0, t; }"
        : "=r"(a) : "l"(p));
    return a;
}
__device__ __forceinline__ void ldsm_x4(uint32_t* r, uint32_t addr) {
    asm volatile("ldmatrix.sync.aligned.m8n8.x4.shared.b16 {%0,%1,%2,%3}, [%4];"
                 : "=r"(r[0]), "=r"(r[1]), "=r"(r[2]), "=r"(r[3]) : "r"(addr));
}
__device__ __forceinline__ void ldsm_x4_t(uint32_t* r, uint32_t addr) {
    asm volatile("ldmatrix.sync.aligned.m8n8.x4.trans.shared.b16 {%0,%1,%2,%3}, [%4];"
                 : "=r"(r[0]), "=r"(r[1]), "=r"(r[2]), "=r"(r[3]) : "r"(addr));
}
__device__ __forceinline__ void mma16816(float* c, const uint32_t* a,
                                         const uint32_t* b) {
    asm volatile(
        "mma.sync.aligned.m16n8k16.row.col.f32.bf16.bf16.f32 "
        "{%0,%1,%2,%3}, {%4,%5,%6,%7}, {%8,%9}, {%0,%1,%2,%3};"
        : "+f"(c[0]), "+f"(c[1]), "+f"(c[2]), "+f"(c[3])
        : "r"(a[0]), "r"(a[1]), "r"(a[2]), "r"(a[3]), "r"(b[0]), "r"(b[1]));
}
__device__ __forceinline__ void cp_async16(uint32_t saddr, const void* g) {
    asm volatile("cp.async.cg.shared.global [%0], [%1], 16;"
                 :: "r"(saddr), "l"(g) : "memory");
}
#define CP_COMMIT() asm volatile("cp.async.commit_group;" ::: "memory")
#define CP_WAIT1()  asm volatile("cp.async.wait_group 1;" ::: "memory")
#define CP_WAIT0()  asm volatile("cp.async.wait_group 0;" ::: "memory")

__device__ __forceinline__ uint32_t bf16pack(float x, float y) {
    __nv_bfloat162 t = __floats2bfloat162_rn(x, y);
    return *(uint32_t*)&t;
}
__device__ __forceinline__ void split_store2(
    __nv_bfloat16* H, __nv_bfloat16* L, size_t idx, float v0, float v1)
{
    __nv_bfloat16 h0 = __float2bfloat16(v0), h1 = __float2bfloat16(v1);
    __nv_bfloat16 l0 = __float2bfloat16(v0 - __bfloat162float(h0));
    __nv_bfloat16 l1 = __float2bfloat16(v1 - __bfloat162float(h1));
    *(__nv_bfloat162*)(H + idx) = __nv_bfloat162(h0, h1);
    *(__nv_bfloat162*)(L + idx) = __nv_bfloat162(l0, l1);
}

// ---------------------------------------------------------------------------
// Split conversions, 4 float4s per thread (MLP=4 for latency-bound HBM path).
// ---------------------------------------------------------------------------
__device__ __forceinline__ void split4(const float* in, __nv_bfloat16* hi,
                                       __nv_bfloat16* lo, int i)
{
    float4 v = ((const float4*)in)[i];
    __nv_bfloat16 h0 = __float2bfloat16(v.x);
    __nv_bfloat16 h1 = __float2bfloat16(v.y);
    __nv_bfloat16 h2 = __float2bfloat16(v.z);
    __nv_bfloat16 h3 = __float2bfloat16(v.w);
    __nv_bfloat16 l0 = __float2bfloat16(v.x - __bfloat162float(h0));
    __nv_bfloat16 l1 = __float2bfloat16(v.y - __bfloat162float(h1));
    __nv_bfloat16 l2 = __float2bfloat16(v.z - __bfloat162float(h2));
    __nv_bfloat16 l3 = __float2bfloat16(v.w - __bfloat162float(h3));
    ((__nv_bfloat162*)hi)[2 * i]     = __nv_bfloat162(h0, h1);
    ((__nv_bfloat162*)hi)[2 * i + 1] = __nv_bfloat162(h2, h3);
    ((__nv_bfloat162*)lo)[2 * i]     = __nv_bfloat162(l0, l1);
    ((__nv_bfloat162*)lo)[2 * i + 1] = __nv_bfloat162(l2, l3);
}

__global__ __launch_bounds__(256) void conv_acts(
    const float* __restrict__ i0, const float* __restrict__ i1,
    const float* __restrict__ i2,
    __nv_bfloat16* __restrict__ hb, __nv_bfloat16* __restrict__ lb, int n4)
{
    int y = blockIdx.y;
    const float* in = (y == 0) ? i0 : (y == 1) ? i1 : i2;
    __nv_bfloat16* hi = hb + (size_t)y * ACT_ELEMS;
    __nv_bfloat16* lo = lb + (size_t)y * ACT_ELEMS;
    int base = blockIdx.x * 1024 + threadIdx.x;
#pragma unroll
    for (int k = 0; k < 4; k++) {
        int i = base + k * 256;
        if (i < n4) split4(in, hi, lo, i);
    }
}

__global__ __launch_bounds__(256) void conv_w(
    const float* __restrict__ w0, const float* __restrict__ w1,
    const float* __restrict__ w2, const float* __restrict__ w3,
    __nv_bfloat16* __restrict__ hb, __nv_bfloat16* __restrict__ lb, int n4)
{
    int y = blockIdx.y;
    const float* in = (y == 0) ? w0 : (y == 1) ? w1 : (y == 2) ? w2 : w3;
    __nv_bfloat16* hi = hb + (size_t)y * DM * DM;
    __nv_bfloat16* lo = lb + (size_t)y * DM * DM;
    int base = blockIdx.x * 1024 + threadIdx.x;
#pragma unroll
    for (int k = 0; k < 4; k++) {
        int i = base + k * 256;
        if (i < n4) split4(in, hi, lo, i);
    }
}

// ---------------------------------------------------------------------------
// Double-buffered HMMA split-bf16 GEMM, 64x128 CTA tiles (halved M to shrink
// wave-tail quantization). 8 warps as 2m x 4n; warp tile 32x32; BK=32.
// MODE 0: merged QKV (blockIdx.z), split-bf16 out [B,H,S,64]; Q scaled QSCALE.
// MODE 3: output projection, fp32 out as [S,B,D].
// SMEM/stage: A(64x40)x2 + B(128x40)x2 = 30720 B; 2 stages = 61440 B.
// ---------------------------------------------------------------------------
#define TSTR 40
#define A_TILE_B 5120
#define B_TILE_B 10240
#define GSTG_B (2 * A_TILE_B + 2 * B_TILE_B)   // 30720

template <int MODE>
__global__ __launch_bounds__(256, 2) void gemm_dbuf(
    const __nv_bfloat16* __restrict__ Xh0, const __nv_bfloat16* __restrict__ Xl0,
    const __nv_bfloat16* __restrict__ Wh0, const __nv_bfloat16* __restrict__ Wl0,
    const float* __restrict__ bias0, const float* __restrict__ bias1,
    const float* __restrict__ bias2,
    __nv_bfloat16* __restrict__ dH0, __nv_bfloat16* __restrict__ dL0,
    float* __restrict__ dF)
{
    extern __shared__ char dyn[];
    const uint32_t sb = smem_u32(dyn);

    const int tid = threadIdx.x;
    const int wid = tid >> 5, lane = tid & 31;
    const int warp_m = wid & 1;          // 2 row groups of 32
    const int warp_n = wid >> 1;         // 4 col groups of 32
    const int rowBase = blockIdx.y * 64;
    const int colBase = blockIdx.x * 128;
    const int z = (MODE == 0) ? blockIdx.z : 0;

    const __nv_bfloat16* Xh = Xh0 + (size_t)z * ACT_ELEMS;
    const __nv_bfloat16* Xl = Xl0 + (size_t)z * ACT_ELEMS;
    const __nv_bfloat16* Wh = Wh0 + (size_t)z * DM * DM;
    const __nv_bfloat16* Wl = Wl0 + (size_t)z * DM * DM;
    const float* bias = (z == 0) ? bias0 : (z == 1) ? bias1 : bias2;
    const float scale = (MODE == 0 && z == 0) ? QSCALE : 1.0f;
    __nv_bfloat16* dH = dH0 + (size_t)z * QKV_ELEMS;
    __nv_bfloat16* dL = dL0 + (size_t)z * QKV_ELEMS;

    float acc[2][4][4];
#pragma unroll
    for (int mi = 0; mi < 2; mi++)
#pragma unroll
        for (int ni = 0; ni < 4; ni++)
#pragma unroll
            for (int e = 0; e < 4; e++) acc[mi][ni][e] = 0.f;

    const uint32_t aoff = (uint32_t)((lane & 15) * (TSTR * 2) + (lane >> 4) * 16);
    const uint32_t boff = (uint32_t)(((lane & 7) + ((lane >> 4) & 1) * 8) * (TSTR * 2)
                                     + ((lane >> 3) & 1) * 16);

    // copy coords: A tile 64x32 = 256 chunks (1/thread); B tile 128x32 = 512 (2/thread)
    const int rA = tid >> 2,            cA = tid & 3;
    const uint32_t soA = (uint32_t)(rA * TSTR + cA * 8) * 2;
    const size_t gA = (size_t)rA * DM + cA * 8;
    const int rB0 = tid >> 2,           cB0 = tid & 3;
    const int rB1 = (tid + 256) >> 2,   cB1 = (tid + 256) & 3;
    const uint32_t soB0 = (uint32_t)(rB0 * TSTR + cB0 * 8) * 2;
    const uint32_t soB1 = (uint32_t)(rB1 * TSTR + cB1 * 8) * 2;
    const size_t gB0 = (size_t)rB0 * DM + cB0 * 8;
    const size_t gB1 = (size_t)rB1 * DM + cB1 * 8;

    auto cp_tile = [&](int c, int st) {
        const __nv_bfloat16* pAh = Xh + (size_t)rowBase * DM + c * 32;
        const __nv_bfloat16* pAl = Xl + (size_t)rowBase * DM + c * 32;
        const __nv_bfloat16* pBh = Wh + (size_t)colBase * DM + c * 32;
        const __nv_bfloat16* pBl = Wl + (size_t)colBase * DM + c * 32;
        uint32_t s0 = sb + st * GSTG_B;
        cp_async16(s0 + soA,                         pAh + gA);
        cp_async16(s0 + A_TILE_B + soA,              pAl + gA);
        cp_async16(s0 + 2 * A_TILE_B + soB0,         pBh + gB0);
        cp_async16(s0 + 2 * A_TILE_B + soB1,         pBh + gB1);
        cp_async16(s0 + 2 * A_TILE_B + B_TILE_B + soB0, pBl + gB0);
        cp_async16(s0 + 2 * A_TILE_B + B_TILE_B + soB1, pBl + gB1);
    };

    cp_tile(0, 0);
    CP_COMMIT();

    for (int c = 0; c < DM / 32; c++) {
        const int st = c & 1;
        const bool more = (c + 1 < DM / 32);
        if (more) { cp_tile(c + 1, st ^ 1); CP_COMMIT(); }
        if (more) CP_WAIT1(); else CP_WAIT0();
        __syncthreads();

        const uint32_t sa_h = sb + st * GSTG_B;
        const uint32_t sa_l = sa_h + A_TILE_B;
        const uint32_t sb_h = sa_h + 2 * A_TILE_B;
        const uint32_t sb_l = sb_h + B_TILE_B;

#pragma unroll
        for (int kk = 0; kk < 2; kk++) {
            const uint32_t kb = (uint32_t)(kk * 32);
            uint32_t ah[2][4], al[2][4];
#pragma unroll
            for (int mi = 0; mi < 2; mi++) {
                uint32_t base = (uint32_t)((warp_m * 32 + mi * 16) * (TSTR * 2)) + kb + aoff;
                ldsm_x4(ah[mi], sa_h + base);
                ldsm_x4(al[mi], sa_l + base);
            }
            uint32_t bhf[2][4], blf[2][4];
#pragma unroll
            for (int nb = 0; nb < 2; nb++) {
                uint32_t base = (uint32_t)((warp_n * 32 + nb * 16) * (TSTR * 2)) + kb + boff;
                ldsm_x4(bhf[nb], sb_h + base);
                ldsm_x4(blf[nb], sb_l + base);
            }
#pragma unroll
            for (int mi = 0; mi < 2; mi++)
#pragma unroll
                for (int ni = 0; ni < 4; ni++) {
                    const uint32_t* fh = &bhf[ni >> 1][(ni & 1) * 2];
                    const uint32_t* fl = &blf[ni >> 1][(ni & 1) * 2];
                    mma16816(acc[mi][ni], ah[mi], fh);
                    mma16816(acc[mi][ni], al[mi], fh);
                    mma16816(acc[mi][ni], ah[mi], fl);
                }
        }
        __syncthreads();
    }

    const int gid = lane >> 2, tig = lane & 3;
#pragma unroll
    for (int mi = 0; mi < 2; mi++) {
#pragma unroll
        for (int ni = 0; ni < 4; ni++) {
            int n = colBase + warp_n * 32 + ni * 8 + tig * 2;
            float b0 = __ldg(bias + n), b1 = __ldg(bias + n + 1);
#pragma unroll
            for (int half = 0; half < 2; half++) {
                int t = rowBase + warp_m * 32 + mi * 16 + gid + half * 8;
                float v0 = (acc[mi][ni][half * 2 + 0] + b0) * scale;
                float v1 = (acc[mi][ni][half * 2 + 1] + b1) * scale;
                if (MODE < 3) {
                    int s = t >> 2, b = t & 3;            // t = s*B + b
                    int h = n >> 6, d = n & 63;           // n = h*64 + d
                    size_t idx = (((size_t)(b * NH + h)) * S_LEN + s) * DKH + d;
                    split_store2(dH, dL, idx, v0, v1);
                } else {
                    int b = t >> 11, s = t & 2047;        // t = b*S + s
                    float* p = dF + ((size_t)(s * NBATCH + b)) * DM + n;
                    *(float2*)p = make_float2(v0, v1);
                }
            }
        }
    }
}

// ---------------------------------------------------------------------------
// Flash attention on HMMA (reverted to the best-measured R13 version):
// no-max softmax (log2e in Q scale), combined 2-stage cp.async K/V ring,
// straight QK -> exp -> PV per 64-key block, 3-term split everywhere.
// ---------------------------------------------------------------------------
#define ASTR 72
#define ABYT (ASTR * 2)
#define KVARR_B 9216
#define KVSTAGE_B (4 * KVARR_B)
#define Q_B 18432
#define ATTN_SMEM (2 * Q_B + 2 * KVSTAGE_B)   // 110592

__global__ __launch_bounds__(256) void attn_hmma(
    const __nv_bfloat16* __restrict__ qkvh, const __nv_bfloat16* __restrict__ qkvl,
    __nv_bfloat16* __restrict__ ch, __nv_bfloat16* __restrict__ cl)
{
    extern __shared__ char smem[];
    const uint32_t sb = smem_u32(smem);
    __nv_bfloat16* sQh = (__nv_bfloat16*)smem;
    __nv_bfloat16* sQl = sQh + Q_B / 2;

    const int tid = threadIdx.x;
    const int wid = tid >> 5, lane = tid & 31;
    const int gid = lane >> 2, tig = lane & 3;
    const int bh = blockIdx.y, qb = blockIdx.x;

    const __nv_bfloat16* qh_b = qkvh + ((size_t)bh * S_LEN + qb * 128) * DKH;
    const __nv_bfloat16* ql_b = qkvl + ((size_t)bh * S_LEN + qb * 128) * DKH;
    const __nv_bfloat16* kh0 = qkvh + (size_t)QKV_ELEMS + (size_t)bh * S_LEN * DKH;
    const __nv_bfloat16* kl0 = qkvl + (size_t)QKV_ELEMS + (size_t)bh * S_LEN * DKH;
    const __nv_bfloat16* vh0 = qkvh + 2 * (size_t)QKV_ELEMS + (size_t)bh * S_LEN * DKH;
    const __nv_bfloat16* vl0 = qkvl + 2 * (size_t)QKV_ELEMS + (size_t)bh * S_LEN * DKH;

#pragma unroll
    for (int l = 0; l < 4; l++) {
        int f = tid + l * 256;
        int r = f >> 3, c8 = f & 7;
        int so = r * ASTR + c8 * 8;
        size_t go = (size_t)r * DKH + c8 * 8;
        *(uint4*)(sQh + so) = *(const uint4*)(qh_b + go);
        *(uint4*)(sQl + so) = *(const uint4*)(ql_b + go);
    }

    const uint32_t qoff = (uint32_t)((wid * 16 + (lane & 15)) * ABYT + (lane >> 4) * 16);
    const uint32_t aQh = sb + qoff;
    const uint32_t aQl = sb + Q_B + qoff;
    const uint32_t krow = (uint32_t)(((lane & 7) + ((lane >> 4) & 1) * 8) * ABYT
                                     + ((lane >> 3) & 1) * 16);
    const uint32_t vrow = (uint32_t)((lane & 15) * ABYT + ((lane >> 4) & 1) * 16);

    const int r0 = tid >> 3,          c80 = tid & 7;
    const int r1 = (tid + 256) >> 3,  c81 = (tid + 256) & 7;
    const uint32_t so0 = (uint32_t)(r0 * ASTR + c80 * 8) * 2;
    const uint32_t so1 = (uint32_t)(r1 * ASTR + c81 * 8) * 2;
    const size_t g0 = (size_t)r0 * DKH + c80 * 8;
    const size_t g1 = (size_t)r1 * DKH + c81 * 8;

    auto cp_kv = [&](int kb, int st) {
        const __nv_bfloat16* pKh = kh0 + (size_t)kb * 64 * DKH;
        const __nv_bfloat16* pKl = kl0 + (size_t)kb * 64 * DKH;
        const __nv_bfloat16* pVh = vh0 + (size_t)kb * 64 * DKH;
        const __nv_bfloat16* pVl = vl0 + (size_t)kb * 64 * DKH;
        uint32_t s0 = sb + 2 * Q_B + st * KVSTAGE_B;
        cp_async16(s0 + so0,               pKh + g0);
        cp_async16(s0 + so1,               pKh + g1);
        cp_async16(s0 + KVARR_B + so0,     pKl + g0);
        cp_async16(s0 + KVARR_B + so1,     pKl + g1);
        cp_async16(s0 + 2 * KVARR_B + so0, pVh + g0);
        cp_async16(s0 + 2 * KVARR_B + so1, pVh + g1);
        cp_async16(s0 + 3 * KVARR_B + so0, pVl + g0);
        cp_async16(s0 + 3 * KVARR_B + so1, pVl + g1);
    };

    float lr0 = 0.f, lr1 = 0.f;
    float oacc[8][4];
#pragma unroll
    for (int i = 0; i < 8; i++)
#pragma unroll
        for (int e = 0; e < 4; e++) oacc[i][e] = 0.f;

    cp_kv(0, 0);
    CP_COMMIT();

    for (int kb = 0; kb < S_LEN / 64; kb++) {
        const int st = kb & 1;
        const bool more = (kb + 1 < S_LEN / 64);
        if (more) { cp_kv(kb + 1, st ^ 1); CP_COMMIT(); }
        if (more) CP_WAIT1(); else CP_WAIT0();
        __syncthreads();

        const uint32_t stBase = sb + 2 * Q_B + st * KVSTAGE_B;
        const uint32_t aKh = stBase + krow;
        const uint32_t aKl = stBase + KVARR_B + krow;
        const uint32_t aVh = stBase + 2 * KVARR_B + vrow;
        const uint32_t aVl = stBase + 3 * KVARR_B + vrow;

        // ---- S = Q K^T (3-term split), warp computes 16x64 ----
        float sacc[8][4];
#pragma unroll
        for (int i = 0; i < 8; i++)
#pragma unroll
            for (int e = 0; e < 4; e++) sacc[i][e] = 0.f;

#pragma unroll
        for (int kk = 0; kk < 4; kk++) {
            uint32_t ah[4], al[4];
            ldsm_x4(ah, aQh + kk * 32);
            ldsm_x4(al, aQl + kk * 32);
#pragma unroll
            for (int nb = 0; nb < 4; nb++) {
                uint32_t bh_[4], bl_[4];
                ldsm_x4(bh_, aKh + (uint32_t)(nb * 16 * ABYT) + kk * 32);
                ldsm_x4(bl_, aKl + (uint32_t)(nb * 16 * ABYT) + kk * 32);
#pragma unroll
                for (int f = 0; f < 2; f++) {
                    mma16816(sacc[nb * 2 + f], ah, &bh_[f * 2]);
                    mma16816(sacc[nb * 2 + f], al, &bh_[f * 2]);
                    mma16816(sacc[nb * 2 + f], ah, &bl_[f * 2]);
                }
            }
        }

        // ---- no-max softmax: p = exp2(s), accumulate row sums ----
        float sum0 = 0.f, sum1 = 0.f;
#pragma unroll
        for (int i = 0; i < 8; i++) {
            sacc[i][0] = exp2f(sacc[i][0]); sum0 += sacc[i][0];
            sacc[i][1] = exp2f(sacc[i][1]); sum0 += sacc[i][1];
            sacc[i][2] = exp2f(sacc[i][2]); sum1 += sacc[i][2];
            sacc[i][3] = exp2f(sacc[i][3]); sum1 += sacc[i][3];
        }
        lr0 += sum0;
        lr1 += sum1;

        // ---- O += P V (3-term split), 4 k16 chunks over the 64 keys ----
#pragma unroll
        for (int c = 0; c < 4; c++) {
            uint32_t pah[4], pal[4];
            {
                float x0 = sacc[2 * c][0],     y0 = sacc[2 * c][1];
                float x1 = sacc[2 * c][2],     y1 = sacc[2 * c][3];
                float x2 = sacc[2 * c + 1][0], y2 = sacc[2 * c + 1][1];
                float x3 = sacc[2 * c + 1][2], y3 = sacc[2 * c + 1][3];
                pah[0] = bf16pack(x0, y0);
                pah[1] = bf16pack(x1, y1);
                pah[2] = bf16pack(x2, y2);
                pah[3] = bf16pack(x3, y3);
                float hx0 = __bfloat162float(__float2bfloat16(x0));
                float hy0 = __bfloat162float(__float2bfloat16(y0));
                float hx1 = __bfloat162float(__float2bfloat16(x1));
                float hy1 = __bfloat162float(__float2bfloat16(y1));
                float hx2 = __bfloat162float(__float2bfloat16(x2));
                float hy2 = __bfloat162float(__float2bfloat16(y2));
                float hx3 = __bfloat162float(__float2bfloat16(x3));
                float hy3 = __bfloat162float(__float2bfloat16(y3));
                pal[0] = bf16pack(x0 - hx0, y0 - hy0);
                pal[1] = bf16pack(x1 - hx1, y1 - hy1);
                pal[2] = bf16pack(x2 - hx2, y2 - hy2);
                pal[3] = bf16pack(x3 - hx3, y3 - hy3);
            }
#pragma unroll
            for (int g = 0; g < 4; g++) {
                uint32_t vbh[4], vbl[4];
                ldsm_x4_t(vbh, aVh + (uint32_t)(c * 16 * ABYT) + g * 32);
                ldsm_x4_t(vbl, aVl + (uint32_t)(c * 16 * ABYT) + g * 32);
#pragma unroll
                for (int f = 0; f < 2; f++) {
                    mma16816(oacc[g * 2 + f], pah, &vbh[f * 2]);
                    mma16816(oacc[g * 2 + f], pal, &vbh[f * 2]);
                    mma16816(oacc[g * 2 + f], pah, &vbl[f * 2]);
                }
            }
        }
        __syncthreads();
    }

    // Quad-reduce row sums (rows gid / gid+8 spread over 4 lanes).
    lr0 += __shfl_xor_sync(0xffffffffu, lr0, 1);
    lr0 += __shfl_xor_sync(0xffffffffu, lr0, 2);
    lr1 += __shfl_xor_sync(0xffffffffu, lr1, 1);
    lr1 += __shfl_xor_sync(0xffffffffu, lr1, 2);

    // Finalize: /l, split-bf16 into ctx buffers [t = b*S+s][h*64+dk].
    const float inv0 = 1.f / lr0, inv1 = 1.f / lr1;
    const int b = bh >> 4, h = bh & 15;
    const int s0 = qb * 128 + wid * 16 + gid;
    const size_t t0 = (size_t)(b * S_LEN + s0) * DM + h * DKH;
    const size_t t1 = (size_t)(b * S_LEN + s0 + 8) * DM + h * DKH;
#pragma unroll
    for (int nt = 0; nt < 8; nt++) {
        int col = nt * 8 + tig * 2;
        split_store2(ch, cl, t0 + col, oacc[nt][0] * inv0, oacc[nt][1] * inv0);
        split_store2(ch, cl, t1 + col, oacc[nt][2] * inv1, oacc[nt][3] * inv1);
    }
}

// ---------------------------------------------------------------------------
// Host launcher
// ---------------------------------------------------------------------------
extern "C" void kernel_launch(void* const* d_in, const int* in_sizes, int n_in,
                              void* d_out, int out_size)
{
    const float* query = (const float*)d_in[0];
    const float* key_  = (const float*)d_in[1];
    const float* value = (const float*)d_in[2];
    const float* Wq = (const float*)d_in[3];
    const float* bq = (const float*)d_in[4];
    const float* Wk = (const float*)d_in[5];
    const float* bk = (const float*)d_in[6];
    const float* Wv = (const float*)d_in[7];
    const float* bv = (const float*)d_in[8];
    const float* Wo = (const float*)d_in[9];
    const float* bo = (const float*)d_in[10];
    float* out = (float*)d_out;

    __nv_bfloat16 *axh, *axl, *qkvh, *qkvl, *cxh, *cxl, *wwh, *wwl;
    cudaGetSymbolAddress((void**)&axh, g_axh);
    cudaGetSymbolAddress((void**)&axl, g_axl);
    cudaGetSymbolAddress((void**)&qkvh, g_qkvh);
    cudaGetSymbolAddress((void**)&qkvl, g_qkvl);
    cudaGetSymbolAddress((void**)&cxh, g_cxh);
    cudaGetSymbolAddress((void**)&cxl, g_cxl);
    cudaGetSymbolAddress((void**)&wwh, g_wwh);
    cudaGetSymbolAddress((void**)&wwl, g_wwl);

    const int nx4 = ACT_ELEMS / 4;     // 2,097,152
    const int nw4 = DM * DM / 4;       // 262,144
    const int gemmSmem = 2 * GSTG_B;   // 61440

    cudaFuncSetAttribute(gemm_dbuf<0>, cudaFuncAttributeMaxDynamicSharedMemorySize,
                         gemmSmem);
    cudaFuncSetAttribute(gemm_dbuf<3>, cudaFuncAttributeMaxDynamicSharedMemorySize,
                         gemmSmem);
    cudaFuncSetAttribute(attn_hmma, cudaFuncAttributeMaxDynamicSharedMemorySize,
                         ATTN_SMEM);

    conv_acts<<<dim3(nx4 / 1024, 3), 256>>>(query, key_, value, axh, axl, nx4);
    conv_w<<<dim3(nw4 / 1024, 4), 256>>>(Wq, Wk, Wv, Wo, wwh, wwl, nw4);

    dim3 qkvGrid(DM / 128, NTOK / 64, 3);   // (8, 128, 3)
    gemm_dbuf<0><<<qkvGrid, 256, gemmSmem>>>(axh, axl, wwh, wwl,
                                             bq, bk, bv, qkvh, qkvl, nullptr);

    dim3 attnGrid(S_LEN / 128, NBATCH * NH);
    attn_hmma<<<attnGrid, 256, ATTN_SMEM>>>(qkvh, qkvl, cxh, cxl);

    dim3 oGrid(DM / 128, NTOK / 64, 1);     // (8, 128)
    gemm_dbuf<3><<<oGrid, 256, gemmSmem>>>(cxh, cxl,
                                           wwh + 3 * (size_t)DM * DM,
                                           wwl + 3 * (size_t)DM * DM,
                                           bo, nullptr, nullptr,
                                           nullptr, nullptr, out);
}